// round 2
// baseline (speedup 1.0000x reference)
#include <cuda_runtime.h>
#include <math.h>
#include <stdint.h>

#define VOCAB  8000
#define HIDDEN 256
#define BATCH  32
#define SEQ    256

// -------- device scratch (no allocations allowed) --------
__device__ float g_WihT[VOCAB * HIDDEN];    // [v][h]  (row gather of embedding)
__device__ float g_WhhT[HIDDEN * HIDDEN];   // [k][j]  (k-major recurrence weights)
__device__ float g_Y[SEQ * BATCH * HIDDEN]; // [s][b][h]

// ---------------- transposes ----------------
__global__ void k_transpose_wih(const float* __restrict__ W) {
    __shared__ float t[32][33];
    int v0 = blockIdx.x * 32, h0 = blockIdx.y * 32;
    for (int i = threadIdx.y; i < 32; i += 8)
        t[i][threadIdx.x] = W[(h0 + i) * VOCAB + v0 + threadIdx.x];
    __syncthreads();
    for (int i = threadIdx.y; i < 32; i += 8)
        g_WihT[(v0 + i) * HIDDEN + h0 + threadIdx.x] = t[threadIdx.x][i];
}

__global__ void k_transpose_whh(const float* __restrict__ W) {
    __shared__ float t[32][33];
    int k0 = blockIdx.x * 32, j0 = blockIdx.y * 32;
    for (int i = threadIdx.y; i < 32; i += 8)
        t[i][threadIdx.x] = W[(j0 + i) * HIDDEN + k0 + threadIdx.x];
    __syncthreads();
    for (int i = threadIdx.y; i < 32; i += 8)
        g_WhhT[(k0 + i) * HIDDEN + j0 + threadIdx.x] = t[threadIdx.x][i];
}

// ---------------- recurrence ----------------
// 16 CTAs, 2 batch elements each, 256 threads.
__global__ void __launch_bounds__(256, 1) k_rnn(
    const int*   __restrict__ X,
    const float* __restrict__ h0,
    const float* __restrict__ b_ih,
    const float* __restrict__ b_hh,
    float*       __restrict__ h_last_out)
{
    __shared__ __align__(16) float hbuf[2][2][HIDDEN]; // [pingpong][b][k]
    __shared__ __align__(16) float part[4][2][HIDDEN]; // [kc][b][j]
    __shared__ float sbih[HIDDEN], sbhh[HIDDEN];

    const int tid = threadIdx.x;
    const int jg  = tid & 63;
    const int kc  = tid >> 6;
    const int b0  = blockIdx.x * 2;

    hbuf[0][0][tid] = h0[(b0 + 0) * HIDDEN + tid];
    hbuf[0][1][tid] = h0[(b0 + 1) * HIDDEN + tid];
    sbih[tid] = b_ih[tid];
    sbhh[tid] = b_hh[tid];
    __syncthreads();

    const float* Wp = g_WhhT + (kc * 64) * HIDDEN + jg * 4;
    int pp = 0;

    for (int s = 0; s < SEQ; s++) {
        float a00 = 0.f, a01 = 0.f, a02 = 0.f, a03 = 0.f;
        float a10 = 0.f, a11 = 0.f, a12 = 0.f, a13 = 0.f;

        const float4* h0p = (const float4*)(&hbuf[pp][0][kc * 64]);
        const float4* h1p = (const float4*)(&hbuf[pp][1][kc * 64]);

        #pragma unroll 4
        for (int kk4 = 0; kk4 < 16; kk4++) {
            float4 hv0 = h0p[kk4];
            float4 hv1 = h1p[kk4];
            float4 w0 = *(const float4*)(Wp + (kk4 * 4 + 0) * HIDDEN);
            float4 w1 = *(const float4*)(Wp + (kk4 * 4 + 1) * HIDDEN);
            float4 w2 = *(const float4*)(Wp + (kk4 * 4 + 2) * HIDDEN);
            float4 w3 = *(const float4*)(Wp + (kk4 * 4 + 3) * HIDDEN);

            a00 += hv0.x * w0.x; a01 += hv0.x * w0.y; a02 += hv0.x * w0.z; a03 += hv0.x * w0.w;
            a10 += hv1.x * w0.x; a11 += hv1.x * w0.y; a12 += hv1.x * w0.z; a13 += hv1.x * w0.w;

            a00 += hv0.y * w1.x; a01 += hv0.y * w1.y; a02 += hv0.y * w1.z; a03 += hv0.y * w1.w;
            a10 += hv1.y * w1.x; a11 += hv1.y * w1.y; a12 += hv1.y * w1.z; a13 += hv1.y * w1.w;

            a00 += hv0.z * w2.x; a01 += hv0.z * w2.y; a02 += hv0.z * w2.z; a03 += hv0.z * w2.w;
            a10 += hv1.z * w2.x; a11 += hv1.z * w2.y; a12 += hv1.z * w2.z; a13 += hv1.z * w2.w;

            a00 += hv0.w * w3.x; a01 += hv0.w * w3.y; a02 += hv0.w * w3.z; a03 += hv0.w * w3.w;
            a10 += hv1.w * w3.x; a11 += hv1.w * w3.y; a12 += hv1.w * w3.z; a13 += hv1.w * w3.w;
        }

        const int jb = jg * 4;
        *(float4*)&part[kc][0][jb] = make_float4(a00, a01, a02, a03);
        *(float4*)&part[kc][1][jb] = make_float4(a10, a11, a12, a13);
        __syncthreads();

        const int j = tid;
        const int tok0 = X[(b0 + 0) * SEQ + s];
        const int tok1 = X[(b0 + 1) * SEQ + s];

        float s0 = part[0][0][j] + part[1][0][j] + part[2][0][j] + part[3][0][j];
        float s1 = part[0][1][j] + part[1][1][j] + part[2][1][j] + part[3][1][j];

        float x0 = g_WihT[tok0 * HIDDEN + j] + sbih[j];
        float x1 = g_WihT[tok1 * HIDDEN + j] + sbih[j];

        float hn0 = tanhf(x0 + s0 + sbhh[j]);
        float hn1 = tanhf(x1 + s1 + sbhh[j]);

        hbuf[pp ^ 1][0][j] = hn0;
        hbuf[pp ^ 1][1][j] = hn1;

        g_Y[((size_t)s * BATCH + b0 + 0) * HIDDEN + j] = hn0;
        g_Y[((size_t)s * BATCH + b0 + 1) * HIDDEN + j] = hn1;
        __syncthreads();
        pp ^= 1;
    }

    h_last_out[(b0 + 0) * HIDDEN + tid] = hbuf[pp][0][tid];
    h_last_out[(b0 + 1) * HIDDEN + tid] = hbuf[pp][1][tid];
}

// ---------------- output GEMM (tf32 tensor cores) ----------------
// C[8192,8000] = Y @ W_out^T + b_out
#define GM 8192
#define GN 8000
#define GK 256
#define TBM 128
#define TBN 128
#define TBK 32
#define SPITCH 136   // 136 mod 32 == 8 -> conflict-free fragment LDS

__device__ __forceinline__ uint32_t f2tf(float x) {
    uint32_t r;
    asm("cvt.rna.tf32.f32 %0, %1;" : "=r"(r) : "f"(x));
    return r;
}

__device__ __forceinline__ void mma_tf32(float c[4], const uint32_t a[4], const uint32_t b[2]) {
    asm volatile(
        "mma.sync.aligned.m16n8k8.row.col.f32.tf32.tf32.f32 "
        "{%0,%1,%2,%3}, {%4,%5,%6,%7}, {%8,%9}, {%0,%1,%2,%3};\n"
        : "+f"(c[0]), "+f"(c[1]), "+f"(c[2]), "+f"(c[3])
        : "r"(a[0]), "r"(a[1]), "r"(a[2]), "r"(a[3]), "r"(b[0]), "r"(b[1]));
}

__global__ void __launch_bounds__(256) k_gemm_tf32(
    const float* __restrict__ W,     // W_out: [GN][GK]
    const float* __restrict__ bias,  // [GN]
    float*       __restrict__ C)     // [GM][GN]
{
    __shared__ uint32_t As[TBK * SPITCH];  // [k][m]
    __shared__ uint32_t Bs[TBK * SPITCH];  // [k][n]

    const int tid  = threadIdx.x;
    const int lane = tid & 31;
    const int warp = tid >> 5;
    const int row0 = blockIdx.y * TBM;
    const int col0 = blockIdx.x * TBN;

    const int warpM = warp >> 2;    // 0..1 -> 64 rows each
    const int warpN = warp & 3;     // 0..3 -> 32 cols each
    const int mW = warpM * 64;
    const int nW = warpN * 32;
    const int tg  = lane & 3;       // threadID_in_group
    const int gid = lane >> 2;      // groupID

    // gmem load assignment: 2 threads per row, 4 float4 each
    const int lm = tid >> 1;              // 0..127
    const int lk = (tid & 1) * 16;        // 0 or 16

    const float* Ag = g_Y + (size_t)(row0 + lm) * GK + lk;
    const int    nb = col0 + lm;
    const float* Bg = W + (size_t)nb * GK + lk;
    const bool   bval = (nb < GN);

    float c[4][4][4];
    #pragma unroll
    for (int mt = 0; mt < 4; mt++)
        #pragma unroll
        for (int nt = 0; nt < 4; nt++)
            #pragma unroll
            for (int r = 0; r < 4; r++) c[mt][nt][r] = 0.f;

    float4 ra[4], rb[4];
    const float4 z4 = make_float4(0.f, 0.f, 0.f, 0.f);

    // initial prefetch
    #pragma unroll
    for (int q = 0; q < 4; q++) {
        ra[q] = *(const float4*)(Ag + q * 4);
        rb[q] = bval ? *(const float4*)(Bg + q * 4) : z4;
    }

    #pragma unroll 1
    for (int it = 0; it < GK / TBK; ++it) {
        // regs -> smem (tf32 round-to-nearest)
        #pragma unroll
        for (int q = 0; q < 4; q++) {
            const int kk = lk + q * 4;
            As[(kk + 0) * SPITCH + lm] = f2tf(ra[q].x);
            As[(kk + 1) * SPITCH + lm] = f2tf(ra[q].y);
            As[(kk + 2) * SPITCH + lm] = f2tf(ra[q].z);
            As[(kk + 3) * SPITCH + lm] = f2tf(ra[q].w);
            Bs[(kk + 0) * SPITCH + lm] = f2tf(rb[q].x);
            Bs[(kk + 1) * SPITCH + lm] = f2tf(rb[q].y);
            Bs[(kk + 2) * SPITCH + lm] = f2tf(rb[q].z);
            Bs[(kk + 3) * SPITCH + lm] = f2tf(rb[q].w);
        }
        __syncthreads();

        // prefetch next K-tile (overlaps with mma phase below)
        if (it + 1 < GK / TBK) {
            const int kn = (it + 1) * TBK;
            #pragma unroll
            for (int q = 0; q < 4; q++) {
                ra[q] = *(const float4*)(Ag + kn + q * 4);
                rb[q] = bval ? *(const float4*)(Bg + kn + q * 4) : z4;
            }
        }

        // compute: 4 k8-steps
        #pragma unroll
        for (int k8 = 0; k8 < 4; k8++) {
            const int kb = k8 * 8;
            uint32_t af[4][4], bf[4][2];
            #pragma unroll
            for (int mt = 0; mt < 4; mt++) {
                const int m = mW + mt * 16;
                af[mt][0] = As[(kb + tg) * SPITCH + m + gid];
                af[mt][1] = As[(kb + tg) * SPITCH + m + gid + 8];
                af[mt][2] = As[(kb + tg + 4) * SPITCH + m + gid];
                af[mt][3] = As[(kb + tg + 4) * SPITCH + m + gid + 8];
            }
            #pragma unroll
            for (int nt = 0; nt < 4; nt++) {
                const int n = nW + nt * 8;
                bf[nt][0] = Bs[(kb + tg) * SPITCH + n + gid];
                bf[nt][1] = Bs[(kb + tg + 4) * SPITCH + n + gid];
            }
            #pragma unroll
            for (int mt = 0; mt < 4; mt++)
                #pragma unroll
                for (int nt = 0; nt < 4; nt++)
                    mma_tf32(c[mt][nt], af[mt], bf[nt]);
        }
        __syncthreads();
    }

    // epilogue: bias + float2 stores (n even, GN even -> pair always in-bounds together)
    #pragma unroll
    for (int mt = 0; mt < 4; mt++) {
        const int m0 = row0 + mW + mt * 16 + gid;
        #pragma unroll
        for (int nt = 0; nt < 4; nt++) {
            const int n0 = col0 + nW + nt * 8 + 2 * tg;
            if (n0 < GN) {
                const float2 bv = *(const float2*)(bias + n0);
                float2 v0 = make_float2(c[mt][nt][0] + bv.x, c[mt][nt][1] + bv.y);
                float2 v1 = make_float2(c[mt][nt][2] + bv.x, c[mt][nt][3] + bv.y);
                *(float2*)(C + (size_t)m0 * GN + n0)       = v0;
                *(float2*)(C + (size_t)(m0 + 8) * GN + n0) = v1;
            }
        }
    }
}

// ---------------- launch ----------------
extern "C" void kernel_launch(void* const* d_in, const int* in_sizes, int n_in,
                              void* d_out, int out_size) {
    const int*   X     = (const int*)d_in[0];
    const float* h0    = (const float*)d_in[1];
    const float* W_ih  = (const float*)d_in[2];
    const float* b_ih  = (const float*)d_in[3];
    const float* W_hh  = (const float*)d_in[4];
    const float* b_hh  = (const float*)d_in[5];
    const float* W_out = (const float*)d_in[6];
    const float* b_out = (const float*)d_in[7];

    float* out    = (float*)d_out;
    float* h_last = out + (size_t)SEQ * BATCH * VOCAB; // tail of output buffer

    dim3 tb(32, 8);
    k_transpose_wih<<<dim3(VOCAB / 32, HIDDEN / 32), tb>>>(W_ih);
    k_transpose_whh<<<dim3(HIDDEN / 32, HIDDEN / 32), tb>>>(W_hh);

    k_rnn<<<BATCH / 2, 256>>>(X, h0, b_ih, b_hh, h_last);

    dim3 grid((GN + TBN - 1) / TBN, GM / TBM); // 63 x 64
    k_gemm_tf32<<<grid, 256>>>(W_out, b_out, out);
}

// round 6
// speedup vs baseline: 1.1660x; 1.1660x over previous
#include <cuda_runtime.h>
#include <math.h>
#include <stdint.h>

#define VOCAB  8000
#define HIDDEN 256
#define BATCH  32
#define SEQ    256

// -------- device scratch (no allocations allowed) --------
__device__ float g_WihT[VOCAB * HIDDEN];    // [v][h]
__device__ float g_Y[SEQ * BATCH * HIDDEN]; // [s][b][h]

// ---------------- transpose W_ih -> [v][h] ----------------
__global__ void k_transpose_wih(const float* __restrict__ W) {
    __shared__ float t[32][33];
    int v0 = blockIdx.x * 32, h0 = blockIdx.y * 32;
    for (int i = threadIdx.y; i < 32; i += 8)
        t[i][threadIdx.x] = W[(h0 + i) * VOCAB + v0 + threadIdx.x];
    __syncthreads();
    for (int i = threadIdx.y; i < 32; i += 8)
        g_WihT[(v0 + i) * HIDDEN + h0 + threadIdx.x] = t[threadIdx.x][i];
}

// ---------------- clustered recurrence ----------------
// Cluster of 4 CTAs per batch element. Rank r owns j in [r*64, r*64+64),
// W_hh slice resident in SMEM; h exchanged via st.shared::cluster each step.
#define RPITCH 260   // 1040B pitch: 1040 % 128 == 16 -> conflict-free LDS.128
#define RNN_SMEM_FLOATS (64 * RPITCH + 2 * HIDDEN + 64)
#define RNN_SMEM_BYTES  (RNN_SMEM_FLOATS * 4)

__device__ __forceinline__ uint32_t smem_u32(const void* p) {
    uint32_t a;
    asm("{ .reg .u64 t; cvta.to.shared.u64 t, %1; cvt.u32.u64 %0, t; }" : "=r"(a) : "l"(p));
    return a;
}

__global__ void __launch_bounds__(256, 1) __cluster_dims__(4, 1, 1)
k_rnn_cl(const int*   __restrict__ X,
         const float* __restrict__ h0,
         const float* __restrict__ Whh,   // [j][k] row-major, used directly
         const float* __restrict__ bih,
         const float* __restrict__ bhh,
         float*       __restrict__ h_last_out)
{
    extern __shared__ float sm[];
    float* sW   = sm;                    // 64 x RPITCH
    float* hbuf = sm + 64 * RPITCH;      // 2 x 256 ping-pong
    float* b2   = hbuf + 2 * HIDDEN;     // 64 combined biases

    const int tid = threadIdx.x;
    uint32_t rank;
    asm("mov.u32 %0, %%cluster_ctarank;" : "=r"(rank));
    const int b  = blockIdx.x >> 2;
    const int j0 = (int)rank * 64;

    for (int idx = tid; idx < 64 * 64; idx += 256) {
        int jl = idx >> 6, c4 = idx & 63;
        float4 v = *(const float4*)(Whh + (size_t)(j0 + jl) * HIDDEN + c4 * 4);
        *(float4*)(sW + jl * RPITCH + c4 * 4) = v;
    }
    hbuf[tid] = h0[b * HIDDEN + tid];
    if (tid < 64) b2[tid] = bih[j0 + tid] + bhh[j0 + tid];
    __syncthreads();
    asm volatile("barrier.cluster.arrive.aligned;" ::: "memory");
    asm volatile("barrier.cluster.wait.aligned;"   ::: "memory");

    const int jj  = tid & 7;
    const int kq  = (tid >> 3) & 3;   // lane bits 3-4 -> shfl_xor 8,16
    const int jhi = tid >> 5;
    const int jl  = jhi * 8 + jj;
    const int j   = j0 + jl;

    const float4* wr = (const float4*)(sW + jl * RPITCH + kq * 64);
    const uint32_t hb_u32 = smem_u32(hbuf);

    int pp = 0;
    // software pipeline: x for step s loaded during step s-1
    int   tok = X[b * SEQ];
    float x   = g_WihT[tok * HIDDEN + j];

    for (int s = 0; s < SEQ; s++) {
        // prefetch next step's embedding gather (hides L2/DRAM latency
        // behind this step's compute + cluster barrier)
        const int   tok_nxt = (s + 1 < SEQ) ? X[b * SEQ + s + 1] : 0;
        const float x_nxt   = g_WihT[tok_nxt * HIDDEN + j];

        const float4* hp = (const float4*)(hbuf + pp * HIDDEN + kq * 64);
        float a0 = 0.f, a1 = 0.f, a2 = 0.f, a3 = 0.f;
        #pragma unroll
        for (int i = 0; i < 16; i += 4) {
            float4 w0 = wr[i],     h40 = hp[i];
            float4 w1 = wr[i + 1], h41 = hp[i + 1];
            float4 w2 = wr[i + 2], h42 = hp[i + 2];
            float4 w3 = wr[i + 3], h43 = hp[i + 3];
            a0 += w0.x*h40.x + w0.y*h40.y + w0.z*h40.z + w0.w*h40.w;
            a1 += w1.x*h41.x + w1.y*h41.y + w1.z*h41.z + w1.w*h41.w;
            a2 += w2.x*h42.x + w2.y*h42.y + w2.z*h42.z + w2.w*h42.w;
            a3 += w3.x*h43.x + w3.y*h43.y + w3.z*h43.z + w3.w*h43.w;
        }
        float acc = (a0 + a1) + (a2 + a3);
        acc += __shfl_xor_sync(0xffffffffu, acc, 8);
        acc += __shfl_xor_sync(0xffffffffu, acc, 16);

        const float hn = tanhf(x + acc + b2[jl]);

        // each kq-lane delivers h_new[j] to cluster rank kq (incl. self)
        const uint32_t laddr = hb_u32 + (uint32_t)(((pp ^ 1) * HIDDEN + j) * 4);
        asm volatile(
            "{ .reg .b32 ra;\n\t"
            "mapa.shared::cluster.u32 ra, %0, %1;\n\t"
            "st.shared::cluster.f32 [ra], %2; }"
            :: "r"(laddr), "r"((uint32_t)kq), "f"(hn) : "memory");

        if (kq == 0)
            g_Y[((size_t)s * BATCH + b) * HIDDEN + j] = hn;

        asm volatile("barrier.cluster.arrive.aligned;" ::: "memory");
        asm volatile("barrier.cluster.wait.aligned;"   ::: "memory");
        pp ^= 1;
        x = x_nxt;
    }

    if (rank == 0)
        h_last_out[b * HIDDEN + tid] = hbuf[pp * HIDDEN + tid];
}

// ---------------- output GEMM (tf32 mma, 64x64 warp tiles) ----------------
#define GM 8192
#define GN 8000
#define GK 256
#define TBM 128
#define TBN 256
#define TBK 16

__device__ __forceinline__ float f2tf(float x) {
    uint32_t r;
    asm("cvt.rna.tf32.f32 %0, %1;" : "=r"(r) : "f"(x));
    return __uint_as_float(r);
}

__device__ __forceinline__ void mma_tf32(float c[4], const uint32_t a[4],
                                         uint32_t b0, uint32_t b1) {
    asm volatile(
        "mma.sync.aligned.m16n8k8.row.col.f32.tf32.tf32.f32 "
        "{%0,%1,%2,%3}, {%4,%5,%6,%7}, {%8,%9}, {%0,%1,%2,%3};\n"
        : "+f"(c[0]), "+f"(c[1]), "+f"(c[2]), "+f"(c[3])
        : "r"(a[0]), "r"(a[1]), "r"(a[2]), "r"(a[3]), "r"(b0), "r"(b1));
}

// quad-interleaved staging: quad(k8,tile16,tg,gid) float4 =
//   {(k=tg,row=gid),(k=tg,row=gid+8),(k=tg+4,row=gid),(k=tg+4,row=gid+8)}
// -> A fragment = one LDS.128; B fragment pair = one LDS.128 (conflict-free).
__global__ void __launch_bounds__(256, 1) k_gemm_tf32(
    const float* __restrict__ W,
    const float* __restrict__ bias,
    float*       __restrict__ C)
{
    __shared__ float4 sa[2][512];    // 16 KB
    __shared__ float4 sb[2][1024];   // 32 KB  (total 48 KB static)

    const int tid  = threadIdx.x;
    const int lane = tid & 31;
    const int warp = tid >> 5;
    const int tg   = lane & 3;
    const int gid  = lane >> 2;
    const int warpM = warp >> 2;
    const int warpN = warp & 3;
    const int row0 = blockIdx.y * TBM;
    const int col0 = blockIdx.x * TBN;

    const int rA = tid >> 1;
    const int kA = (tid & 1) * 8;
    const float* Ag = g_Y + (size_t)(row0 + rA) * GK + kA;
    const int   nb  = col0 + tid;
    const float* Bg = W + (size_t)nb * GK;
    const bool  bval = (nb < GN);

    const int tileA = rA >> 4, gidA = rA & 7, halfA = (rA >> 3) & 1;
    const int tileB = tid >> 4, gidB = tid & 7, halfB = (tid >> 3) & 1;

    float c[4][8][4];
    #pragma unroll
    for (int mt = 0; mt < 4; mt++)
        #pragma unroll
        for (int nt = 0; nt < 8; nt++)
            #pragma unroll
            for (int r = 0; r < 4; r++) c[mt][nt][r] = 0.f;

    const float4 z4 = make_float4(0.f, 0.f, 0.f, 0.f);
    float4 pra[2], prb[4];

    pra[0] = *(const float4*)(Ag);
    pra[1] = *(const float4*)(Ag + 4);
    #pragma unroll
    for (int q = 0; q < 4; q++)
        prb[q] = bval ? *(const float4*)(Bg + q * 4) : z4;

    {
        float* saf = (float*)sa[0];
        float* sbf = (float*)sb[0];
        #pragma unroll
        for (int q = 0; q < 2; q++) {
            const int k0 = kA + q * 4;
            const int base = ((k0 >> 3) * 8 + tileA) * 128 + gidA * 4 + ((k0 >> 2) & 1) * 2 + halfA;
            const float4 v = pra[q];
            saf[base +  0] = f2tf(v.x); saf[base + 32] = f2tf(v.y);
            saf[base + 64] = f2tf(v.z); saf[base + 96] = f2tf(v.w);
        }
        #pragma unroll
        for (int q = 0; q < 4; q++) {
            const int k0 = q * 4;
            const int base = ((k0 >> 3) * 16 + tileB) * 128 + gidB * 4 + ((k0 >> 2) & 1) * 2 + halfB;
            const float4 v = prb[q];
            sbf[base +  0] = f2tf(v.x); sbf[base + 32] = f2tf(v.y);
            sbf[base + 64] = f2tf(v.z); sbf[base + 96] = f2tf(v.w);
        }
    }
    __syncthreads();

    #pragma unroll 1
    for (int it = 0; it < GK / TBK; ++it) {
        const int cur = it & 1;

        if (it + 1 < GK / TBK) {
            const int kc = (it + 1) * TBK;
            pra[0] = *(const float4*)(Ag + kc);
            pra[1] = *(const float4*)(Ag + kc + 4);
            #pragma unroll
            for (int q = 0; q < 4; q++)
                prb[q] = bval ? *(const float4*)(Bg + kc + q * 4) : z4;
        }

        #pragma unroll
        for (int k8 = 0; k8 < 2; k8++) {
            float4 afq[4], bq[4];
            #pragma unroll
            for (int mt = 0; mt < 4; mt++)
                afq[mt] = sa[cur][((k8 * 8 + warpM * 4 + mt) * 4 + tg) * 8 + gid];
            #pragma unroll
            for (int p = 0; p < 4; p++)
                bq[p] = sb[cur][((k8 * 16 + warpN * 4 + p) * 4 + tg) * 8 + gid];

            #pragma unroll
            for (int mt = 0; mt < 4; mt++) {
                uint32_t a[4] = { __float_as_uint(afq[mt].x), __float_as_uint(afq[mt].y),
                                  __float_as_uint(afq[mt].z), __float_as_uint(afq[mt].w) };
                #pragma unroll
                for (int p = 0; p < 4; p++) {
                    mma_tf32(c[mt][2 * p],     a, __float_as_uint(bq[p].x), __float_as_uint(bq[p].z));
                    mma_tf32(c[mt][2 * p + 1], a, __float_as_uint(bq[p].y), __float_as_uint(bq[p].w));
                }
            }
        }

        if (it + 1 < GK / TBK) {
            float* saf = (float*)sa[cur ^ 1];
            float* sbf = (float*)sb[cur ^ 1];
            #pragma unroll
            for (int q = 0; q < 2; q++) {
                const int k0 = kA + q * 4;
                const int base = ((k0 >> 3) * 8 + tileA) * 128 + gidA * 4 + ((k0 >> 2) & 1) * 2 + halfA;
                const float4 v = pra[q];
                saf[base +  0] = f2tf(v.x); saf[base + 32] = f2tf(v.y);
                saf[base + 64] = f2tf(v.z); saf[base + 96] = f2tf(v.w);
            }
            #pragma unroll
            for (int q = 0; q < 4; q++) {
                const int k0 = q * 4;
                const int base = ((k0 >> 3) * 16 + tileB) * 128 + gidB * 4 + ((k0 >> 2) & 1) * 2 + halfB;
                const float4 v = prb[q];
                sbf[base +  0] = f2tf(v.x); sbf[base + 32] = f2tf(v.y);
                sbf[base + 64] = f2tf(v.z); sbf[base + 96] = f2tf(v.w);
            }
        }
        __syncthreads();
    }

    #pragma unroll
    for (int mt = 0; mt < 4; mt++) {
        const int r0 = row0 + warpM * 64 + mt * 16 + gid;
        #pragma unroll
        for (int nt = 0; nt < 8; nt++) {
            const int col = col0 + warpN * 64 + nt * 8 + tg * 2;
            if (col < GN) {
                const float2 bv = *(const float2*)(bias + col);
                float2 v0 = make_float2(c[mt][nt][0] + bv.x, c[mt][nt][1] + bv.y);
                float2 v1 = make_float2(c[mt][nt][2] + bv.x, c[mt][nt][3] + bv.y);
                *(float2*)(C + (size_t)r0 * GN + col)       = v0;
                *(float2*)(C + (size_t)(r0 + 8) * GN + col) = v1;
            }
        }
    }
}

// ---------------- launch ----------------
extern "C" void kernel_launch(void* const* d_in, const int* in_sizes, int n_in,
                              void* d_out, int out_size) {
    const int*   X     = (const int*)d_in[0];
    const float* h0    = (const float*)d_in[1];
    const float* W_ih  = (const float*)d_in[2];
    const float* b_ih  = (const float*)d_in[3];
    const float* W_hh  = (const float*)d_in[4];
    const float* b_hh  = (const float*)d_in[5];
    const float* W_out = (const float*)d_in[6];
    const float* b_out = (const float*)d_in[7];

    float* out    = (float*)d_out;
    float* h_last = out + (size_t)SEQ * BATCH * VOCAB;

    cudaFuncSetAttribute(k_rnn_cl, cudaFuncAttributeMaxDynamicSharedMemorySize,
                         RNN_SMEM_BYTES);

    dim3 tb(32, 8);
    k_transpose_wih<<<dim3(VOCAB / 32, HIDDEN / 32), tb>>>(W_ih);

    k_rnn_cl<<<BATCH * 4, 256, RNN_SMEM_BYTES>>>(X, h0, W_hh, b_ih, b_hh, h_last);

    dim3 grid((GN + TBN - 1) / TBN, GM / TBM); // 32 x 64
    k_gemm_tf32<<<grid, 256>>>(W_out, b_out, out);
}

// round 10
// speedup vs baseline: 1.3726x; 1.1772x over previous
#include <cuda_runtime.h>
#include <math.h>
#include <stdint.h>

#define VOCAB  8000
#define HIDDEN 256
#define BATCH  32
#define SEQ    256

// -------- device scratch (no allocations allowed) --------
__device__ float g_WihT[VOCAB * HIDDEN];    // [v][h]
__device__ float g_Y[SEQ * BATCH * HIDDEN]; // [s][b][h]

// ---------------- transpose W_ih -> [v][h] ----------------
__global__ void k_transpose_wih(const float* __restrict__ W) {
    __shared__ float t[32][33];
    int v0 = blockIdx.x * 32, h0 = blockIdx.y * 32;
    for (int i = threadIdx.y; i < 32; i += 8)
        t[i][threadIdx.x] = W[(h0 + i) * VOCAB + v0 + threadIdx.x];
    __syncthreads();
    for (int i = threadIdx.y; i < 32; i += 8)
        g_WihT[(v0 + i) * HIDDEN + h0 + threadIdx.x] = t[threadIdx.x][i];
}

// ---------------- clustered recurrence (W_hh in REGISTERS) ----------------
// Cluster of 4 CTAs per batch element. Rank r owns j in [r*64, r*64+64).
// Thread (jl, kq): holds W_hh[j0+jl][kq*64 .. kq*64+64) in 64 registers.
// Per step: broadcast h-LDS, 64 FMA, shfl-reduce over kq, tanh, DSMEM fanout.
__device__ __forceinline__ uint32_t smem_u32(const void* p) {
    uint32_t a;
    asm("{ .reg .u64 t; cvta.to.shared.u64 t, %1; cvt.u32.u64 %0, t; }" : "=r"(a) : "l"(p));
    return a;
}

__global__ void __launch_bounds__(256, 1) __cluster_dims__(4, 1, 1)
k_rnn_cl(const int*   __restrict__ X,
         const float* __restrict__ h0,
         const float* __restrict__ Whh,   // [j][k] row-major
         const float* __restrict__ bih,
         const float* __restrict__ bhh,
         float*       __restrict__ h_last_out)
{
    __shared__ __align__(16) float hbuf[2][HIDDEN]; // ping-pong h
    __shared__ int toks[SEQ];

    const int tid = threadIdx.x;
    uint32_t rank;
    asm("mov.u32 %0, %%cluster_ctarank;" : "=r"(rank));
    const int b  = blockIdx.x >> 2;
    const int j0 = (int)rank * 64;

    const int jj  = tid & 7;
    const int kq  = (tid >> 3) & 3;   // lane bits 3-4 -> shfl_xor 8,16
    const int jhi = tid >> 5;
    const int jl  = jhi * 8 + jj;
    const int j   = j0 + jl;

    // one-time loads
    hbuf[0][tid] = h0[b * HIDDEN + tid];
    toks[tid]    = X[b * SEQ + tid];
    const float b2r = bih[j] + bhh[j];

    // W_hh slice -> registers (16 x LDG.128)
    float4 wv[16];
    {
        const float4* wg = (const float4*)(Whh + (size_t)j * HIDDEN + kq * 64);
        #pragma unroll
        for (int i = 0; i < 16; i++) wv[i] = wg[i];
    }
    __syncthreads();
    asm volatile("barrier.cluster.arrive.aligned;" ::: "memory");
    asm volatile("barrier.cluster.wait.aligned;"   ::: "memory");

    const uint32_t hb_u32 = smem_u32(hbuf);

    int pp = 0;
    float x = g_WihT[toks[0] * HIDDEN + j];   // x for step 0

    for (int s = 0; s < SEQ; s++) {
        // dot over this thread's 64-k chunk (W in regs, h broadcast-LDS)
        const float4* hp = (const float4*)(hbuf[pp] + kq * 64);
        float a0 = 0.f, a1 = 0.f, a2 = 0.f, a3 = 0.f;
        #pragma unroll
        for (int i = 0; i < 16; i += 4) {
            float4 h40 = hp[i],     h41 = hp[i + 1];
            float4 h42 = hp[i + 2], h43 = hp[i + 3];
            a0 += wv[i].x*h40.x + wv[i].y*h40.y + wv[i].z*h40.z + wv[i].w*h40.w;
            a1 += wv[i+1].x*h41.x + wv[i+1].y*h41.y + wv[i+1].z*h41.z + wv[i+1].w*h41.w;
            a2 += wv[i+2].x*h42.x + wv[i+2].y*h42.y + wv[i+2].z*h42.z + wv[i+2].w*h42.w;
            a3 += wv[i+3].x*h43.x + wv[i+3].y*h43.y + wv[i+3].z*h43.z + wv[i+3].w*h43.w;
        }
        float acc = (a0 + a1) + (a2 + a3);
        acc += __shfl_xor_sync(0xffffffffu, acc, 8);
        acc += __shfl_xor_sync(0xffffffffu, acc, 16);

        const float hn = tanhf(x + acc + b2r);

        // fan h_new[j] out to cluster rank kq (incl. self)
        const uint32_t laddr = hb_u32 + (uint32_t)(((pp ^ 1) * HIDDEN + j) * 4);
        asm volatile(
            "{ .reg .b32 ra;\n\t"
            "mapa.shared::cluster.u32 ra, %0, %1;\n\t"
            "st.shared::cluster.f32 [ra], %2; }"
            :: "r"(laddr), "r"((uint32_t)kq), "f"(hn) : "memory");

        asm volatile("barrier.cluster.arrive.aligned;" ::: "memory");

        // hidden under barrier skew: g_Y store + next-step embedding prefetch
        if (kq == 0)
            g_Y[((size_t)s * BATCH + b) * HIDDEN + j] = hn;
        const int tok_nxt = (s + 1 < SEQ) ? toks[s + 1] : 0;
        const float x_nxt = g_WihT[tok_nxt * HIDDEN + j];

        asm volatile("barrier.cluster.wait.aligned;" ::: "memory");
        pp ^= 1;
        x = x_nxt;
    }

    if (rank == 0)
        h_last_out[b * HIDDEN + tid] = hbuf[pp][tid];
}

// ---------------- output GEMM (tf32 mma, 64x64 warp tiles) ----------------
#define GM 8192
#define GN 8000
#define GK 256
#define TBM 128
#define TBN 256
#define TBK 16

__device__ __forceinline__ float f2tf(float x) {
    uint32_t r;
    asm("cvt.rna.tf32.f32 %0, %1;" : "=r"(r) : "f"(x));
    return __uint_as_float(r);
}

__device__ __forceinline__ void mma_tf32(float c[4], const uint32_t a[4],
                                         uint32_t b0, uint32_t b1) {
    asm volatile(
        "mma.sync.aligned.m16n8k8.row.col.f32.tf32.tf32.f32 "
        "{%0,%1,%2,%3}, {%4,%5,%6,%7}, {%8,%9}, {%0,%1,%2,%3};\n"
        : "+f"(c[0]), "+f"(c[1]), "+f"(c[2]), "+f"(c[3])
        : "r"(a[0]), "r"(a[1]), "r"(a[2]), "r"(a[3]), "r"(b0), "r"(b1));
}

// quad-interleaved staging: quad(k8,tile16,tg,gid) float4 =
//   {(k=tg,row=gid),(k=tg,row=gid+8),(k=tg+4,row=gid),(k=tg+4,row=gid+8)}
__global__ void __launch_bounds__(256, 1) k_gemm_tf32(
    const float* __restrict__ W,
    const float* __restrict__ bias,
    float*       __restrict__ C)
{
    __shared__ float4 sa[2][512];    // 16 KB
    __shared__ float4 sb[2][1024];   // 32 KB

    const int tid  = threadIdx.x;
    const int lane = tid & 31;
    const int warp = tid >> 5;
    const int tg   = lane & 3;
    const int gid  = lane >> 2;
    const int warpM = warp >> 2;
    const int warpN = warp & 3;
    const int row0 = blockIdx.y * TBM;
    const int col0 = blockIdx.x * TBN;

    const int rA = tid >> 1;
    const int kA = (tid & 1) * 8;
    const float* Ag = g_Y + (size_t)(row0 + rA) * GK + kA;
    const int   nb  = col0 + tid;
    const float* Bg = W + (size_t)nb * GK;
    const bool  bval = (nb < GN);

    const int tileA = rA >> 4, gidA = rA & 7, halfA = (rA >> 3) & 1;
    const int tileB = tid >> 4, gidB = tid & 7, halfB = (tid >> 3) & 1;

    float c[4][8][4];
    #pragma unroll
    for (int mt = 0; mt < 4; mt++)
        #pragma unroll
        for (int nt = 0; nt < 8; nt++)
            #pragma unroll
            for (int r = 0; r < 4; r++) c[mt][nt][r] = 0.f;

    const float4 z4 = make_float4(0.f, 0.f, 0.f, 0.f);
    float4 pra[2], prb[4];

    pra[0] = *(const float4*)(Ag);
    pra[1] = *(const float4*)(Ag + 4);
    #pragma unroll
    for (int q = 0; q < 4; q++)
        prb[q] = bval ? *(const float4*)(Bg + q * 4) : z4;

    {
        float* saf = (float*)sa[0];
        float* sbf = (float*)sb[0];
        #pragma unroll
        for (int q = 0; q < 2; q++) {
            const int k0 = kA + q * 4;
            const int base = ((k0 >> 3) * 8 + tileA) * 128 + gidA * 4 + ((k0 >> 2) & 1) * 2 + halfA;
            const float4 v = pra[q];
            saf[base +  0] = f2tf(v.x); saf[base + 32] = f2tf(v.y);
            saf[base + 64] = f2tf(v.z); saf[base + 96] = f2tf(v.w);
        }
        #pragma unroll
        for (int q = 0; q < 4; q++) {
            const int k0 = q * 4;
            const int base = ((k0 >> 3) * 16 + tileB) * 128 + gidB * 4 + ((k0 >> 2) & 1) * 2 + halfB;
            const float4 v = prb[q];
            sbf[base +  0] = f2tf(v.x); sbf[base + 32] = f2tf(v.y);
            sbf[base + 64] = f2tf(v.z); sbf[base + 96] = f2tf(v.w);
        }
    }
    __syncthreads();

    #pragma unroll 1
    for (int it = 0; it < GK / TBK; ++it) {
        const int cur = it & 1;

        if (it + 1 < GK / TBK) {
            const int kc = (it + 1) * TBK;
            pra[0] = *(const float4*)(Ag + kc);
            pra[1] = *(const float4*)(Ag + kc + 4);
            #pragma unroll
            for (int q = 0; q < 4; q++)
                prb[q] = bval ? *(const float4*)(Bg + kc + q * 4) : z4;
        }

        #pragma unroll
        for (int k8 = 0; k8 < 2; k8++) {
            float4 afq[4], bq[4];
            #pragma unroll
            for (int mt = 0; mt < 4; mt++)
                afq[mt] = sa[cur][((k8 * 8 + warpM * 4 + mt) * 4 + tg) * 8 + gid];
            #pragma unroll
            for (int p = 0; p < 4; p++)
                bq[p] = sb[cur][((k8 * 16 + warpN * 4 + p) * 4 + tg) * 8 + gid];

            #pragma unroll
            for (int mt = 0; mt < 4; mt++) {
                uint32_t a[4] = { __float_as_uint(afq[mt].x), __float_as_uint(afq[mt].y),
                                  __float_as_uint(afq[mt].z), __float_as_uint(afq[mt].w) };
                #pragma unroll
                for (int p = 0; p < 4; p++) {
                    mma_tf32(c[mt][2 * p],     a, __float_as_uint(bq[p].x), __float_as_uint(bq[p].z));
                    mma_tf32(c[mt][2 * p + 1], a, __float_as_uint(bq[p].y), __float_as_uint(bq[p].w));
                }
            }
        }

        if (it + 1 < GK / TBK) {
            float* saf = (float*)sa[cur ^ 1];
            float* sbf = (float*)sb[cur ^ 1];
            #pragma unroll
            for (int q = 0; q < 2; q++) {
                const int k0 = kA + q * 4;
                const int base = ((k0 >> 3) * 8 + tileA) * 128 + gidA * 4 + ((k0 >> 2) & 1) * 2 + halfA;
                const float4 v = pra[q];
                saf[base +  0] = f2tf(v.x); saf[base + 32] = f2tf(v.y);
                saf[base + 64] = f2tf(v.z); saf[base + 96] = f2tf(v.w);
            }
            #pragma unroll
            for (int q = 0; q < 4; q++) {
                const int k0 = q * 4;
                const int base = ((k0 >> 3) * 16 + tileB) * 128 + gidB * 4 + ((k0 >> 2) & 1) * 2 + halfB;
                const float4 v = prb[q];
                sbf[base +  0] = f2tf(v.x); sbf[base + 32] = f2tf(v.y);
                sbf[base + 64] = f2tf(v.z); sbf[base + 96] = f2tf(v.w);
            }
        }
        __syncthreads();
    }

    #pragma unroll
    for (int mt = 0; mt < 4; mt++) {
        const int r0 = row0 + warpM * 64 + mt * 16 + gid;
        #pragma unroll
        for (int nt = 0; nt < 8; nt++) {
            const int col = col0 + warpN * 64 + nt * 8 + tg * 2;
            if (col < GN) {
                const float2 bv = *(const float2*)(bias + col);
                float2 v0 = make_float2(c[mt][nt][0] + bv.x, c[mt][nt][1] + bv.y);
                float2 v1 = make_float2(c[mt][nt][2] + bv.x, c[mt][nt][3] + bv.y);
                *(float2*)(C + (size_t)r0 * GN + col)       = v0;
                *(float2*)(C + (size_t)(r0 + 8) * GN + col) = v1;
            }
        }
    }
}

// ---------------- launch ----------------
extern "C" void kernel_launch(void* const* d_in, const int* in_sizes, int n_in,
                              void* d_out, int out_size) {
    const int*   X     = (const int*)d_in[0];
    const float* h0    = (const float*)d_in[1];
    const float* W_ih  = (const float*)d_in[2];
    const float* b_ih  = (const float*)d_in[3];
    const float* W_hh  = (const float*)d_in[4];
    const float* b_hh  = (const float*)d_in[5];
    const float* W_out = (const float*)d_in[6];
    const float* b_out = (const float*)d_in[7];

    float* out    = (float*)d_out;
    float* h_last = out + (size_t)SEQ * BATCH * VOCAB;

    dim3 tb(32, 8);
    k_transpose_wih<<<dim3(VOCAB / 32, HIDDEN / 32), tb>>>(W_ih);

    k_rnn_cl<<<BATCH * 4, 256>>>(X, h0, W_hh, b_ih, b_hh, h_last);

    dim3 grid((GN + TBN - 1) / TBN, GM / TBM); // 32 x 64
    k_gemm_tf32<<<grid, 256>>>(W_out, b_out, out);
}